// round 12
// baseline (speedup 1.0000x reference)
#include <cuda_runtime.h>
#include <cuda_bf16.h>
#include <math.h>
#include <stdint.h>

// Problem constants
#define BROWS 4096
#define EDIM  512
#define DDIM  768
#define NT    32          // 4096 / 128 j-tiles

// ---------------- device scratch (allocation-free) ----------------
__device__ __nv_bfloat16 g_wti[EDIM * DDIM];    // W_img^T bf16 [512,768] K-contig
__device__ __nv_bfloat16 g_wtt[EDIM * DDIM];    // W_txt^T bf16
__device__ __nv_bfloat16 g_imgh[BROWS * EDIM];  // normalized bf16
__device__ __nv_bfloat16 g_txth[BROWS * EDIM];
__device__ float g_sy[BROWS];
__device__ float g_partS[NT * BROWS];
__device__ float g_partD[NT * BROWS];
__device__ float g_row[64];                     // rowloss block partials

// ---------------- PTX helpers (plain sm_80-era PTX) ----------------
__device__ __forceinline__ uint32_t s2u(const void* p) {
    uint32_t a;
    asm("{ .reg .u64 t; cvta.to.shared.u64 t, %1; cvt.u32.u64 %0, t; }"
        : "=r"(a) : "l"(p));
    return a;
}
__device__ __forceinline__ void cp16(uint32_t s, const void* g) {
    asm volatile("cp.async.cg.shared.global [%0], [%1], 16;" :: "r"(s), "l"(g));
}
__device__ __forceinline__ void cp_commit() { asm volatile("cp.async.commit_group;"); }
__device__ __forceinline__ void cp_wait0()  { asm volatile("cp.async.wait_group 0;"); }
__device__ __forceinline__ void cp_wait1()  { asm volatile("cp.async.wait_group 1;"); }

__device__ __forceinline__ void ldsm4(uint32_t* r, uint32_t addr) {
    asm volatile("ldmatrix.sync.aligned.m8n8.x4.shared.b16 {%0,%1,%2,%3}, [%4];"
                 : "=r"(r[0]), "=r"(r[1]), "=r"(r[2]), "=r"(r[3]) : "r"(addr));
}
__device__ __forceinline__ void mma16816(float* c, const uint32_t* a,
                                         uint32_t b0, uint32_t b1) {
    asm volatile(
        "mma.sync.aligned.m16n8k16.row.col.f32.bf16.bf16.f32 "
        "{%0,%1,%2,%3}, {%4,%5,%6,%7}, {%8,%9}, {%0,%1,%2,%3};"
        : "+f"(c[0]), "+f"(c[1]), "+f"(c[2]), "+f"(c[3])
        : "r"(a[0]), "r"(a[1]), "r"(a[2]), "r"(a[3]), "r"(b0), "r"(b1));
}

// Load ROWS x 64 bf16 (128B rows, SW128 xor swizzle) via cp.async.
template<int ROWS, int KEL, int THREADS>
__device__ __forceinline__ void load_rows(uint32_t sdst,
    const __nv_bfloat16* __restrict__ G, int k0)
{
    const int tid = threadIdx.x;
    #pragma unroll
    for (int i = 0; i < ROWS * 8 / THREADS; i++) {
        int idx = i * THREADS + tid;
        int row = idx >> 3, ch = idx & 7;
        uint32_t soff = (uint32_t)row * 128u + ((uint32_t)(ch ^ (row & 7)) << 4);
        cp16(sdst + soff, G + (size_t)row * KEL + k0 + ch * 8);
    }
}

// W [K=768, N=512] fp32 -> W^T [512, 768] bf16. Tile 64k x 32n, 256 threads.
__global__ void transpose2_k(const float* __restrict__ Wi, const float* __restrict__ Wt2)
{
    const int which = blockIdx.z;
    const float* W = which ? Wt2 : Wi;
    __nv_bfloat16* Wt = which ? g_wtt : g_wti;
    __shared__ float t[64][33];
    const int n0 = blockIdx.x * 32, k0 = blockIdx.y * 64;
    const int tx = threadIdx.x & 31, ty = threadIdx.x >> 5;   // 32 x 8
    #pragma unroll
    for (int i = 0; i < 8; i++) {
        int r = ty + i * 8;
        t[r][tx] = W[(size_t)(k0 + r) * EDIM + n0 + tx];
    }
    __syncthreads();
    #pragma unroll
    for (int i = 0; i < 4; i++) {
        int n = ty + i * 8;
        *(__nv_bfloat162*)(Wt + (size_t)(n0 + n) * DDIM + k0 + tx * 2) =
            __floats2bfloat162_rn(t[tx * 2][n], t[tx * 2 + 1][n]);
    }
}

// ---------------------------------------------------------------------------
// Fused fp32->bf16 convert + embed GEMM + row L2-normalize.  (unchanged)
// ---------------------------------------------------------------------------
#define EN_STAGE 73728
#define EN_SMEM  (3 * EN_STAGE)   // 221184

__global__ __launch_bounds__(256, 1) void embed_norm_k(
    const float* __restrict__ images, const float* __restrict__ texts)
{
    extern __shared__ char smem[];
    const uint32_t sb = s2u(smem);
    const int which = blockIdx.y;
    const float* Afp = (which ? texts : images) + (size_t)blockIdx.x * 64 * DDIM;
    const __nv_bfloat16* Wt = which ? g_wtt : g_wti;
    __nv_bfloat16* out = which ? g_txth : g_imgh;
    const int m0 = blockIdx.x * 64;

    const int tid = threadIdx.x, lane = tid & 31, w = tid >> 5;
    const int l15 = lane & 15, lhi = lane >> 4;
    const int g = lane >> 2, tig = lane & 3;

    const int row0 = tid >> 3,          ch0 = tid & 7;
    const int row1 = (256 + tid) >> 3,  ch1 = tid & 7;
    const uint32_t aoff0 = (uint32_t)row0 * 128u + ((uint32_t)(ch0 ^ (row0 & 7)) << 4);
    const uint32_t aoff1 = (uint32_t)row1 * 128u + ((uint32_t)(ch1 ^ (row1 & 7)) << 4);
    const float* asrc0 = Afp + (size_t)row0 * DDIM + ch0 * 8;
    const float* asrc1 = Afp + (size_t)row1 * DDIM + ch1 * 8;

    float c[4][8][4] = {};
    constexpr int ITERS = DDIM / 64;   // 12

    #pragma unroll
    for (int p = 0; p < 2; p++) {
        load_rows<512, DDIM, 256>(sb + p * EN_STAGE + 8192, Wt, p * 64);
        cp_commit();
    }
    #pragma unroll
    for (int p = 0; p < 2; p++) {
        const int k0 = p * 64;
        float4 f0 = *(const float4*)(asrc0 + k0);
        float4 f1 = *(const float4*)(asrc0 + k0 + 4);
        float4 f2 = *(const float4*)(asrc1 + k0);
        float4 f3 = *(const float4*)(asrc1 + k0 + 4);
        uint4 v0, v1;
        ((__nv_bfloat162*)&v0)[0] = __floats2bfloat162_rn(f0.x, f0.y);
        ((__nv_bfloat162*)&v0)[1] = __floats2bfloat162_rn(f0.z, f0.w);
        ((__nv_bfloat162*)&v0)[2] = __floats2bfloat162_rn(f1.x, f1.y);
        ((__nv_bfloat162*)&v0)[3] = __floats2bfloat162_rn(f1.z, f1.w);
        ((__nv_bfloat162*)&v1)[0] = __floats2bfloat162_rn(f2.x, f2.y);
        ((__nv_bfloat162*)&v1)[1] = __floats2bfloat162_rn(f2.z, f2.w);
        ((__nv_bfloat162*)&v1)[2] = __floats2bfloat162_rn(f3.x, f3.y);
        ((__nv_bfloat162*)&v1)[3] = __floats2bfloat162_rn(f3.z, f3.w);
        *(uint4*)(smem + p * EN_STAGE + aoff0) = v0;
        *(uint4*)(smem + p * EN_STAGE + aoff1) = v1;
    }

    float4 pf0, pf1, pf2, pf3;
    for (int s = 0; s < ITERS; s++) {
        if (s == ITERS - 1) cp_wait0(); else cp_wait1();
        __syncthreads();
        const bool pre = (s + 2 < ITERS);
        if (pre) {
            const int d = (s + 2) % 3;
            load_rows<512, DDIM, 256>(sb + d * EN_STAGE + 8192, Wt, (s + 2) * 64);
            cp_commit();
            const int k0 = (s + 2) * 64;
            pf0 = *(const float4*)(asrc0 + k0);
            pf1 = *(const float4*)(asrc0 + k0 + 4);
            pf2 = *(const float4*)(asrc1 + k0);
            pf3 = *(const float4*)(asrc1 + k0 + 4);
        }
        const uint32_t abase = sb + (s % 3) * EN_STAGE;
        const uint32_t bbase = abase + 8192;
        #pragma unroll
        for (int kk = 0; kk < 4; kk++) {
            const int ch = kk * 2 + lhi;
            uint32_t a[4][4];
            #pragma unroll
            for (int mt = 0; mt < 4; mt++) {
                int r = l15 + mt * 16;
                ldsm4(a[mt], abase + (uint32_t)r * 128u + ((uint32_t)(ch ^ (r & 7)) << 4));
            }
            uint32_t b[4][4];
            #pragma unroll
            for (int h = 0; h < 4; h++) {
                int r = w * 64 + h * 16 + l15;
                ldsm4(b[h], bbase + (uint32_t)r * 128u + ((uint32_t)(ch ^ (r & 7)) << 4));
            }
            #pragma unroll
            for (int mt = 0; mt < 4; mt++)
                #pragma unroll
                for (int nt = 0; nt < 8; nt++)
                    mma16816(c[mt][nt], a[mt], b[nt >> 1][nt & 1], b[nt >> 1][2 + (nt & 1)]);
        }
        if (pre) {
            const int d = (s + 2) % 3;
            uint4 v0, v1;
            ((__nv_bfloat162*)&v0)[0] = __floats2bfloat162_rn(pf0.x, pf0.y);
            ((__nv_bfloat162*)&v0)[1] = __floats2bfloat162_rn(pf0.z, pf0.w);
            ((__nv_bfloat162*)&v0)[2] = __floats2bfloat162_rn(pf1.x, pf1.y);
            ((__nv_bfloat162*)&v0)[3] = __floats2bfloat162_rn(pf1.z, pf1.w);
            ((__nv_bfloat162*)&v1)[0] = __floats2bfloat162_rn(pf2.x, pf2.y);
            ((__nv_bfloat162*)&v1)[1] = __floats2bfloat162_rn(pf2.z, pf2.w);
            ((__nv_bfloat162*)&v1)[2] = __floats2bfloat162_rn(pf3.x, pf3.y);
            ((__nv_bfloat162*)&v1)[3] = __floats2bfloat162_rn(pf3.z, pf3.w);
            *(uint4*)(smem + d * EN_STAGE + aoff0) = v0;
            *(uint4*)(smem + d * EN_STAGE + aoff1) = v1;
        }
    }
    __syncthreads();

    float* nsm = (float*)smem;
    #pragma unroll
    for (int mt = 0; mt < 4; mt++) {
        float plo = 0.f, phi = 0.f;
        #pragma unroll
        for (int nt = 0; nt < 8; nt++) {
            plo += c[mt][nt][0] * c[mt][nt][0] + c[mt][nt][1] * c[mt][nt][1];
            phi += c[mt][nt][2] * c[mt][nt][2] + c[mt][nt][3] * c[mt][nt][3];
        }
        #pragma unroll
        for (int o = 1; o < 4; o <<= 1) {
            plo += __shfl_xor_sync(0xffffffffu, plo, o);
            phi += __shfl_xor_sync(0xffffffffu, phi, o);
        }
        if (tig == 0) {
            nsm[(mt * 16 + g) * 8 + w] = plo;
            nsm[(mt * 16 + g + 8) * 8 + w] = phi;
        }
    }
    __syncthreads();
    if (tid < 64) {
        float s = 0.f;
        #pragma unroll
        for (int i = 0; i < 8; i++) s += nsm[tid * 8 + i];
        nsm[512 + tid] = 1.0f / sqrtf(s);
    }
    __syncthreads();
    #pragma unroll
    for (int mt = 0; mt < 4; mt++) {
        const int rl = mt * 16 + g;
        const float rlo = nsm[512 + rl], rhi = nsm[512 + rl + 8];
        #pragma unroll
        for (int nt = 0; nt < 8; nt++) {
            const int col = w * 64 + nt * 8 + tig * 2;
            *(__nv_bfloat162*)(out + (size_t)(m0 + rl) * EDIM + col) =
                __floats2bfloat162_rn(c[mt][nt][0] * rlo, c[mt][nt][1] * rlo);
            *(__nv_bfloat162*)(out + (size_t)(m0 + rl + 8) * EDIM + col) =
                __floats2bfloat162_rn(c[mt][nt][2] * rhi, c[mt][nt][3] * rhi);
        }
    }
}

// ---------------------------------------------------------------------------
// s_y[i] = dot(imgh_i, txth_{labels[i]}) — 2 rows per warp, 8 LDG.128 in flight.
// ---------------------------------------------------------------------------
__global__ void sy_k(const int* __restrict__ labels)
{
    const int lane = threadIdx.x & 31;
    const int r0 = blockIdx.x * 16 + (threadIdx.x >> 5) * 2;
    const int r1 = r0 + 1;
    const int y0 = __ldg(labels + r0), y1 = __ldg(labels + r1);
    const uint4* a0 = (const uint4*)(g_imgh + (size_t)r0 * EDIM);
    const uint4* b0 = (const uint4*)(g_txth + (size_t)y0 * EDIM);
    const uint4* a1 = (const uint4*)(g_imgh + (size_t)r1 * EDIM);
    const uint4* b1 = (const uint4*)(g_txth + (size_t)y1 * EDIM);
    uint4 av00 = a0[lane], av01 = a0[32 + lane];
    uint4 bv00 = b0[lane], bv01 = b0[32 + lane];
    uint4 av10 = a1[lane], av11 = a1[32 + lane];
    uint4 bv10 = b1[lane], bv11 = b1[32 + lane];
    float s0 = 0.f, s1 = 0.f;
    #pragma unroll
    for (int q = 0; q < 4; q++) {
        float2 x, yv;
        x = __bfloat1622float2(((const __nv_bfloat162*)&av00)[q]);
        yv = __bfloat1622float2(((const __nv_bfloat162*)&bv00)[q]);
        s0 += x.x * yv.x + x.y * yv.y;
        x = __bfloat1622float2(((const __nv_bfloat162*)&av01)[q]);
        yv = __bfloat1622float2(((const __nv_bfloat162*)&bv01)[q]);
        s0 += x.x * yv.x + x.y * yv.y;
        x = __bfloat1622float2(((const __nv_bfloat162*)&av10)[q]);
        yv = __bfloat1622float2(((const __nv_bfloat162*)&bv10)[q]);
        s1 += x.x * yv.x + x.y * yv.y;
        x = __bfloat1622float2(((const __nv_bfloat162*)&av11)[q]);
        yv = __bfloat1622float2(((const __nv_bfloat162*)&bv11)[q]);
        s1 += x.x * yv.x + x.y * yv.y;
    }
    #pragma unroll
    for (int o = 16; o > 0; o >>= 1) {
        s0 += __shfl_xor_sync(0xffffffffu, s0, o);
        s1 += __shfl_xor_sync(0xffffffffu, s1, o);
    }
    if (lane == 0) { g_sy[r0] = s0; g_sy[r1] = s1; }
}

// ---------------------------------------------------------------------------
// Logits GEMM (imgh @ txth^T) + fused softmax-partials epilogue.
// 128x128 tile, 128 threads (4 warps 2x2, warp tile 64x64), **occupancy 3**.
// 2-stage cp.async ring (64KB) so 3 CTAs fit in smem; regs capped at 170 —
// B fragments streamed (one ldsm4 live at a time) to fit under the cap.
// Smem: stage st at st*32768: A [0,16K), B [16K,32K);
// slabC @65536, slabR @66048, ssy @66560, pS @67072(1K), pD @68096(1K).
// ---------------------------------------------------------------------------
#define LG_SMEM 69120

__global__ __launch_bounds__(128, 3) void logits_mma(const int* __restrict__ labels,
                                                     const float* __restrict__ lsp)
{
    extern __shared__ char smem[];
    const uint32_t sb = s2u(smem);
    int*   slabC = (int*)(smem + 65536);
    int*   slabR = (int*)(smem + 66048);
    float* ssy   = (float*)(smem + 66560);
    float* pS    = (float*)(smem + 67072);
    float* pD    = (float*)(smem + 68096);
    const int m0 = blockIdx.y * 128, n0 = blockIdx.x * 128;
    const int tid = threadIdx.x;
    slabC[tid] = labels[n0 + tid];
    slabR[tid] = labels[m0 + tid];
    ssy[tid]   = g_sy[m0 + tid];

    const __nv_bfloat16* A = g_imgh + (size_t)m0 * EDIM;
    const __nv_bfloat16* B = g_txth + (size_t)n0 * EDIM;
    const int lane = tid & 31, warp = tid >> 5;
    const int l15 = lane & 15, lhi = lane >> 4;
    const int warp_m = warp >> 1, warp_n = warp & 1;   // 2 x 2

    float c[4][8][4] = {};          // 64 rows x 64 cols per warp
    const int arow = warp_m * 64 + l15;
    const int brow = warp_n * 64 + l15;

    constexpr int ITERS = EDIM / 64;   // 8
    #pragma unroll
    for (int p = 0; p < 2; p++) {
        load_rows<128, EDIM, 128>(sb + p * 32768u,          A, p * 64);
        load_rows<128, EDIM, 128>(sb + p * 32768u + 16384u, B, p * 64);
        cp_commit();
    }
    cp_wait1();                       // stage 0 resident
    __syncthreads();

    for (int s = 0; s < ITERS; s++) {
        const uint32_t abase = sb + (uint32_t)(s & 1) * 32768u;
        const uint32_t bbase = abase + 16384u;
        #pragma unroll
        for (int kk = 0; kk < 4; kk++) {
            const int ch = kk * 2 + lhi;
            uint32_t a[4][4];
            #pragma unroll
            for (int mt = 0; mt < 4; mt++) {
                int r = arow + mt * 16;
                ldsm4(a[mt], abase + (uint32_t)r * 128u + ((uint32_t)(ch ^ (r & 7)) << 4));
            }
            #pragma unroll
            for (int h = 0; h < 4; h++) {            // streamed B fragments
                uint32_t b[4];
                int r = brow + h * 16;
                ldsm4(b, bbase + (uint32_t)r * 128u + ((uint32_t)(ch ^ (r & 7)) << 4));
                #pragma unroll
                for (int mt = 0; mt < 4; mt++) {
                    mma16816(c[mt][h * 2],     a[mt], b[0], b[2]);
                    mma16816(c[mt][h * 2 + 1], a[mt], b[1], b[3]);
                }
            }
        }
        __syncthreads();                              // done reading buf s&1
        if (s + 2 < ITERS) {
            load_rows<128, EDIM, 128>(abase,          A, (s + 2) * 64);
            load_rows<128, EDIM, 128>(abase + 16384u, B, (s + 2) * 64);
            cp_commit();
        }
        if (s + 1 < ITERS) {
            if (s + 2 < ITERS) cp_wait1(); else cp_wait0();
            __syncthreads();                          // stage s+1 visible
        }
    }

    // ---- epilogue: exp2 + masked row-sum partials ----
    const int g = lane >> 2, tig = lane & 3;
    const float scale = expf(__ldg(lsp));
    const float s2 = scale * 1.4426950408889634f;   // log2(e)*scale
    const float b2 = -s2;

    int labc[16];
    #pragma unroll
    for (int t = 0; t < 16; t++)
        labc[t] = slabC[warp_n * 64 + (t >> 1) * 8 + tig * 2 + (t & 1)];
    const int jbase = n0 + warp_n * 64 + tig * 2;

    #pragma unroll
    for (int mt = 0; mt < 4; mt++) {
        const int rl = warp_m * 64 + mt * 16 + g;
        const int lab_lo = slabR[rl], lab_hi = slabR[rl + 8];
        const float sy_lo = ssy[rl], sy_hi = ssy[rl + 8];
        float Slo = 0.f, Dlo = 0.f, Shi = 0.f, Dhi = 0.f;
        #pragma unroll
        for (int nt = 0; nt < 8; nt++) {
            const int lab0 = labc[nt * 2], lab1 = labc[nt * 2 + 1];
            const int j0 = jbase + nt * 8, j1 = j0 + 1;
            float v, e;
            v = c[mt][nt][0]; e = exp2f(fmaf(v, s2, b2)); Slo += e;
            if (lab0 != lab_lo && j0 != lab_lo && v > sy_lo) Dlo += e;
            v = c[mt][nt][1]; e = exp2f(fmaf(v, s2, b2)); Slo += e;
            if (lab1 != lab_lo && j1 != lab_lo && v > sy_lo) Dlo += e;
            v = c[mt][nt][2]; e = exp2f(fmaf(v, s2, b2)); Shi += e;
            if (lab0 != lab_hi && j0 != lab_hi && v > sy_hi) Dhi += e;
            v = c[mt][nt][3]; e = exp2f(fmaf(v, s2, b2)); Shi += e;
            if (lab1 != lab_hi && j1 != lab_hi && v > sy_hi) Dhi += e;
        }
        #pragma unroll
        for (int o = 1; o < 4; o <<= 1) {
            Slo += __shfl_xor_sync(0xffffffffu, Slo, o);
            Dlo += __shfl_xor_sync(0xffffffffu, Dlo, o);
            Shi += __shfl_xor_sync(0xffffffffu, Shi, o);
            Dhi += __shfl_xor_sync(0xffffffffu, Dhi, o);
        }
        if (tig == 0) {
            pS[rl * 2 + warp_n] = Slo;  pD[rl * 2 + warp_n] = Dlo;
            pS[(rl + 8) * 2 + warp_n] = Shi;  pD[(rl + 8) * 2 + warp_n] = Dhi;
        }
    }
    __syncthreads();
    {
        float S = pS[tid * 2] + pS[tid * 2 + 1];
        float D = pD[tid * 2] + pD[tid * 2 + 1];
        g_partS[(size_t)blockIdx.x * BROWS + m0 + tid] = S;
        g_partD[(size_t)blockIdx.x * BROWS + m0 + tid] = D;
    }
}

// ---------------------------------------------------------------------------
// Per-row loss terms; each of 32 blocks emits one partial sum (deterministic).
// ---------------------------------------------------------------------------
__global__ void rowloss_k(const float* __restrict__ lsp)
{
    const int row = blockIdx.x * blockDim.x + threadIdx.x;   // 32 x 128
    const float scale = expf(*lsp);
    float S = 0.f, D = 0.f;
    #pragma unroll
    for (int t = 0; t < NT; t++) {
        S += g_partS[t * BROWS + row];
        D += g_partD[t * BROWS + row];
    }
    const float sy = g_sy[row] * scale;
    const float logp = (sy - scale) - logf(S);
    const float p = expf(logp);
    const float denom = D / S;
    const float cmp = (D > 0.0f) ? p / (denom + 1e-10f) : 0.0f;
    float v = cmp - logp;
    #pragma unroll
    for (int o = 16; o > 0; o >>= 1) v += __shfl_xor_sync(0xffffffffu, v, o);
    __shared__ float red[4];
    if ((threadIdx.x & 31) == 0) red[threadIdx.x >> 5] = v;
    __syncthreads();
    if (threadIdx.x == 0)
        g_row[blockIdx.x] = red[0] + red[1] + red[2] + red[3];
}

__global__ void final_k(float* __restrict__ out)
{
    const int lane = threadIdx.x;   // 32
    float s = g_row[lane];
    #pragma unroll
    for (int o = 16; o > 0; o >>= 1) s += __shfl_xor_sync(0xffffffffu, s, o);
    if (lane == 0) out[0] = s / (float)BROWS;
}

// ---------------------------------------------------------------------------
extern "C" void kernel_launch(void* const* d_in, const int* in_sizes, int n_in,
                              void* d_out, int out_size)
{
    const float* images = (const float*)d_in[0];
    const float* texts  = (const float*)d_in[1];
    const int*   labels = (const int*)d_in[2];
    const float* W_img  = (const float*)d_in[3];
    const float* W_txt  = (const float*)d_in[4];
    const float* lscale = (const float*)d_in[5];
    float* out = (float*)d_out;

    // Idempotent; needed for >48KB dynamic smem.
    cudaFuncSetAttribute(embed_norm_k, cudaFuncAttributeMaxDynamicSharedMemorySize, EN_SMEM);
    cudaFuncSetAttribute(logits_mma,   cudaFuncAttributeMaxDynamicSharedMemorySize, LG_SMEM);

    transpose2_k<<<dim3(EDIM / 32, DDIM / 64, 2), 256>>>(W_img, W_txt);

    embed_norm_k<<<dim3(BROWS / 64, 2), 256, EN_SMEM>>>(images, texts);

    sy_k<<<BROWS / 16, 256>>>(labels);

    logits_mma<<<dim3(NT, NT), 128, LG_SMEM>>>(labels, lscale);

    rowloss_k<<<32, 128>>>(lscale);
    final_k<<<1, 32>>>(out);
}

// round 13
// speedup vs baseline: 1.1446x; 1.1446x over previous
#include <cuda_runtime.h>
#include <cuda_bf16.h>
#include <math.h>
#include <stdint.h>

// Problem constants
#define BROWS 4096
#define EDIM  512
#define DDIM  768
#define NT    32          // 4096 / 128 j-tiles

// ---------------- device scratch (allocation-free) ----------------
__device__ __nv_bfloat16 g_wti[EDIM * DDIM];    // W_img^T bf16 [512,768] K-contig
__device__ __nv_bfloat16 g_wtt[EDIM * DDIM];    // W_txt^T bf16
__device__ __nv_bfloat16 g_imgh[BROWS * EDIM];  // normalized bf16
__device__ __nv_bfloat16 g_txth[BROWS * EDIM];
__device__ float g_sy[BROWS];
__device__ float g_partS[NT * BROWS];
__device__ float g_partD[NT * BROWS];
__device__ float g_row[64];                     // rowloss block partials

// ---------------- PTX helpers (plain sm_80-era PTX) ----------------
__device__ __forceinline__ uint32_t s2u(const void* p) {
    uint32_t a;
    asm("{ .reg .u64 t; cvta.to.shared.u64 t, %1; cvt.u32.u64 %0, t; }"
        : "=r"(a) : "l"(p));
    return a;
}
__device__ __forceinline__ void cp16(uint32_t s, const void* g) {
    asm volatile("cp.async.cg.shared.global [%0], [%1], 16;" :: "r"(s), "l"(g));
}
__device__ __forceinline__ void cp_commit() { asm volatile("cp.async.commit_group;"); }
__device__ __forceinline__ void cp_wait0()  { asm volatile("cp.async.wait_group 0;"); }
__device__ __forceinline__ void cp_wait1()  { asm volatile("cp.async.wait_group 1;"); }

__device__ __forceinline__ void ldsm4(uint32_t* r, uint32_t addr) {
    asm volatile("ldmatrix.sync.aligned.m8n8.x4.shared.b16 {%0,%1,%2,%3}, [%4];"
                 : "=r"(r[0]), "=r"(r[1]), "=r"(r[2]), "=r"(r[3]) : "r"(addr));
}
__device__ __forceinline__ void mma16816(float* c, const uint32_t* a,
                                         uint32_t b0, uint32_t b1) {
    asm volatile(
        "mma.sync.aligned.m16n8k16.row.col.f32.bf16.bf16.f32 "
        "{%0,%1,%2,%3}, {%4,%5,%6,%7}, {%8,%9}, {%0,%1,%2,%3};"
        : "+f"(c[0]), "+f"(c[1]), "+f"(c[2]), "+f"(c[3])
        : "r"(a[0]), "r"(a[1]), "r"(a[2]), "r"(a[3]), "r"(b0), "r"(b1));
}

// Load ROWS x 64 bf16 (128B rows, SW128 xor swizzle) via cp.async.
template<int ROWS, int KEL, int THREADS>
__device__ __forceinline__ void load_rows(uint32_t sdst,
    const __nv_bfloat16* __restrict__ G, int k0)
{
    const int tid = threadIdx.x;
    #pragma unroll
    for (int i = 0; i < ROWS * 8 / THREADS; i++) {
        int idx = i * THREADS + tid;
        int row = idx >> 3, ch = idx & 7;
        uint32_t soff = (uint32_t)row * 128u + ((uint32_t)(ch ^ (row & 7)) << 4);
        cp16(sdst + soff, G + (size_t)row * KEL + k0 + ch * 8);
    }
}

// Quarter-load for the logits kernel: 2 A-chunks + 2 B-chunks per kk (128 thr).
__device__ __forceinline__ void load_q(int kk, uint32_t sa, uint32_t sbm,
    const __nv_bfloat16* __restrict__ A, const __nv_bfloat16* __restrict__ B, int k0)
{
    const int tid = threadIdx.x;
    #pragma unroll
    for (int i = kk * 2; i < kk * 2 + 2; i++) {
        int idx = i * 128 + tid;
        int row = idx >> 3, ch = idx & 7;
        uint32_t soff = (uint32_t)row * 128u + ((uint32_t)(ch ^ (row & 7)) << 4);
        cp16(sa + soff,  A + (size_t)row * EDIM + k0 + ch * 8);
        cp16(sbm + soff, B + (size_t)row * EDIM + k0 + ch * 8);
    }
}

// W [K=768, N=512] fp32 -> W^T [512, 768] bf16. Tile 64k x 32n, 256 threads.
__global__ void transpose2_k(const float* __restrict__ Wi, const float* __restrict__ Wt2)
{
    const int which = blockIdx.z;
    const float* W = which ? Wt2 : Wi;
    __nv_bfloat16* Wt = which ? g_wtt : g_wti;
    __shared__ float t[64][33];
    const int n0 = blockIdx.x * 32, k0 = blockIdx.y * 64;
    const int tx = threadIdx.x & 31, ty = threadIdx.x >> 5;   // 32 x 8
    #pragma unroll
    for (int i = 0; i < 8; i++) {
        int r = ty + i * 8;
        t[r][tx] = W[(size_t)(k0 + r) * EDIM + n0 + tx];
    }
    __syncthreads();
    #pragma unroll
    for (int i = 0; i < 4; i++) {
        int n = ty + i * 8;
        *(__nv_bfloat162*)(Wt + (size_t)(n0 + n) * DDIM + k0 + tx * 2) =
            __floats2bfloat162_rn(t[tx * 2][n], t[tx * 2 + 1][n]);
    }
}

// ---------------------------------------------------------------------------
// Fused fp32->bf16 convert + embed GEMM + row L2-normalize.
// ---------------------------------------------------------------------------
#define EN_STAGE 73728
#define EN_SMEM  (3 * EN_STAGE)   // 221184

__global__ __launch_bounds__(256, 1) void embed_norm_k(
    const float* __restrict__ images, const float* __restrict__ texts)
{
    extern __shared__ char smem[];
    const uint32_t sb = s2u(smem);
    const int which = blockIdx.y;
    const float* Afp = (which ? texts : images) + (size_t)blockIdx.x * 64 * DDIM;
    const __nv_bfloat16* Wt = which ? g_wtt : g_wti;
    __nv_bfloat16* out = which ? g_txth : g_imgh;
    const int m0 = blockIdx.x * 64;

    const int tid = threadIdx.x, lane = tid & 31, w = tid >> 5;
    const int l15 = lane & 15, lhi = lane >> 4;
    const int g = lane >> 2, tig = lane & 3;

    const int row0 = tid >> 3,          ch0 = tid & 7;
    const int row1 = (256 + tid) >> 3,  ch1 = tid & 7;
    const uint32_t aoff0 = (uint32_t)row0 * 128u + ((uint32_t)(ch0 ^ (row0 & 7)) << 4);
    const uint32_t aoff1 = (uint32_t)row1 * 128u + ((uint32_t)(ch1 ^ (row1 & 7)) << 4);
    const float* asrc0 = Afp + (size_t)row0 * DDIM + ch0 * 8;
    const float* asrc1 = Afp + (size_t)row1 * DDIM + ch1 * 8;

    float c[4][8][4] = {};
    constexpr int ITERS = DDIM / 64;   // 12

    #pragma unroll
    for (int p = 0; p < 2; p++) {
        load_rows<512, DDIM, 256>(sb + p * EN_STAGE + 8192, Wt, p * 64);
        cp_commit();
    }
    #pragma unroll
    for (int p = 0; p < 2; p++) {
        const int k0 = p * 64;
        float4 f0 = *(const float4*)(asrc0 + k0);
        float4 f1 = *(const float4*)(asrc0 + k0 + 4);
        float4 f2 = *(const float4*)(asrc1 + k0);
        float4 f3 = *(const float4*)(asrc1 + k0 + 4);
        uint4 v0, v1;
        ((__nv_bfloat162*)&v0)[0] = __floats2bfloat162_rn(f0.x, f0.y);
        ((__nv_bfloat162*)&v0)[1] = __floats2bfloat162_rn(f0.z, f0.w);
        ((__nv_bfloat162*)&v0)[2] = __floats2bfloat162_rn(f1.x, f1.y);
        ((__nv_bfloat162*)&v0)[3] = __floats2bfloat162_rn(f1.z, f1.w);
        ((__nv_bfloat162*)&v1)[0] = __floats2bfloat162_rn(f2.x, f2.y);
        ((__nv_bfloat162*)&v1)[1] = __floats2bfloat162_rn(f2.z, f2.w);
        ((__nv_bfloat162*)&v1)[2] = __floats2bfloat162_rn(f3.x, f3.y);
        ((__nv_bfloat162*)&v1)[3] = __floats2bfloat162_rn(f3.z, f3.w);
        *(uint4*)(smem + p * EN_STAGE + aoff0) = v0;
        *(uint4*)(smem + p * EN_STAGE + aoff1) = v1;
    }

    float4 pf0, pf1, pf2, pf3;
    for (int s = 0; s < ITERS; s++) {
        if (s == ITERS - 1) cp_wait0(); else cp_wait1();
        __syncthreads();
        const bool pre = (s + 2 < ITERS);
        if (pre) {
            const int d = (s + 2) % 3;
            load_rows<512, DDIM, 256>(sb + d * EN_STAGE + 8192, Wt, (s + 2) * 64);
            cp_commit();
            const int k0 = (s + 2) * 64;
            pf0 = *(const float4*)(asrc0 + k0);
            pf1 = *(const float4*)(asrc0 + k0 + 4);
            pf2 = *(const float4*)(asrc1 + k0);
            pf3 = *(const float4*)(asrc1 + k0 + 4);
        }
        const uint32_t abase = sb + (s % 3) * EN_STAGE;
        const uint32_t bbase = abase + 8192;
        #pragma unroll
        for (int kk = 0; kk < 4; kk++) {
            const int ch = kk * 2 + lhi;
            uint32_t a[4][4];
            #pragma unroll
            for (int mt = 0; mt < 4; mt++) {
                int r = l15 + mt * 16;
                ldsm4(a[mt], abase + (uint32_t)r * 128u + ((uint32_t)(ch ^ (r & 7)) << 4));
            }
            uint32_t b[4][4];
            #pragma unroll
            for (int h = 0; h < 4; h++) {
                int r = w * 64 + h * 16 + l15;
                ldsm4(b[h], bbase + (uint32_t)r * 128u + ((uint32_t)(ch ^ (r & 7)) << 4));
            }
            #pragma unroll
            for (int mt = 0; mt < 4; mt++)
                #pragma unroll
                for (int nt = 0; nt < 8; nt++)
                    mma16816(c[mt][nt], a[mt], b[nt >> 1][nt & 1], b[nt >> 1][2 + (nt & 1)]);
        }
        if (pre) {
            const int d = (s + 2) % 3;
            uint4 v0, v1;
            ((__nv_bfloat162*)&v0)[0] = __floats2bfloat162_rn(pf0.x, pf0.y);
            ((__nv_bfloat162*)&v0)[1] = __floats2bfloat162_rn(pf0.z, pf0.w);
            ((__nv_bfloat162*)&v0)[2] = __floats2bfloat162_rn(pf1.x, pf1.y);
            ((__nv_bfloat162*)&v0)[3] = __floats2bfloat162_rn(pf1.z, pf1.w);
            ((__nv_bfloat162*)&v1)[0] = __floats2bfloat162_rn(pf2.x, pf2.y);
            ((__nv_bfloat162*)&v1)[1] = __floats2bfloat162_rn(pf2.z, pf2.w);
            ((__nv_bfloat162*)&v1)[2] = __floats2bfloat162_rn(pf3.x, pf3.y);
            ((__nv_bfloat162*)&v1)[3] = __floats2bfloat162_rn(pf3.z, pf3.w);
            *(uint4*)(smem + d * EN_STAGE + aoff0) = v0;
            *(uint4*)(smem + d * EN_STAGE + aoff1) = v1;
        }
    }
    __syncthreads();

    float* nsm = (float*)smem;
    #pragma unroll
    for (int mt = 0; mt < 4; mt++) {
        float plo = 0.f, phi = 0.f;
        #pragma unroll
        for (int nt = 0; nt < 8; nt++) {
            plo += c[mt][nt][0] * c[mt][nt][0] + c[mt][nt][1] * c[mt][nt][1];
            phi += c[mt][nt][2] * c[mt][nt][2] + c[mt][nt][3] * c[mt][nt][3];
        }
        #pragma unroll
        for (int o = 1; o < 4; o <<= 1) {
            plo += __shfl_xor_sync(0xffffffffu, plo, o);
            phi += __shfl_xor_sync(0xffffffffu, phi, o);
        }
        if (tig == 0) {
            nsm[(mt * 16 + g) * 8 + w] = plo;
            nsm[(mt * 16 + g + 8) * 8 + w] = phi;
        }
    }
    __syncthreads();
    if (tid < 64) {
        float s = 0.f;
        #pragma unroll
        for (int i = 0; i < 8; i++) s += nsm[tid * 8 + i];
        nsm[512 + tid] = 1.0f / sqrtf(s);
    }
    __syncthreads();
    #pragma unroll
    for (int mt = 0; mt < 4; mt++) {
        const int rl = mt * 16 + g;
        const float rlo = nsm[512 + rl], rhi = nsm[512 + rl + 8];
        #pragma unroll
        for (int nt = 0; nt < 8; nt++) {
            const int col = w * 64 + nt * 8 + tig * 2;
            *(__nv_bfloat162*)(out + (size_t)(m0 + rl) * EDIM + col) =
                __floats2bfloat162_rn(c[mt][nt][0] * rlo, c[mt][nt][1] * rlo);
            *(__nv_bfloat162*)(out + (size_t)(m0 + rl + 8) * EDIM + col) =
                __floats2bfloat162_rn(c[mt][nt][2] * rhi, c[mt][nt][3] * rhi);
        }
    }
}

// ---------------------------------------------------------------------------
// s_y[i] = dot(imgh_i, txth_{labels[i]}) — 2 rows per warp, 8 LDG.128 in flight.
// ---------------------------------------------------------------------------
__global__ void sy_k(const int* __restrict__ labels)
{
    const int lane = threadIdx.x & 31;
    const int r0 = blockIdx.x * 16 + (threadIdx.x >> 5) * 2;
    const int r1 = r0 + 1;
    const int y0 = __ldg(labels + r0), y1 = __ldg(labels + r1);
    const uint4* a0 = (const uint4*)(g_imgh + (size_t)r0 * EDIM);
    const uint4* b0 = (const uint4*)(g_txth + (size_t)y0 * EDIM);
    const uint4* a1 = (const uint4*)(g_imgh + (size_t)r1 * EDIM);
    const uint4* b1 = (const uint4*)(g_txth + (size_t)y1 * EDIM);
    uint4 av00 = a0[lane], av01 = a0[32 + lane];
    uint4 bv00 = b0[lane], bv01 = b0[32 + lane];
    uint4 av10 = a1[lane], av11 = a1[32 + lane];
    uint4 bv10 = b1[lane], bv11 = b1[32 + lane];
    float s0 = 0.f, s1 = 0.f;
    #pragma unroll
    for (int q = 0; q < 4; q++) {
        float2 x, yv;
        x = __bfloat1622float2(((const __nv_bfloat162*)&av00)[q]);
        yv = __bfloat1622float2(((const __nv_bfloat162*)&bv00)[q]);
        s0 += x.x * yv.x + x.y * yv.y;
        x = __bfloat1622float2(((const __nv_bfloat162*)&av01)[q]);
        yv = __bfloat1622float2(((const __nv_bfloat162*)&bv01)[q]);
        s0 += x.x * yv.x + x.y * yv.y;
        x = __bfloat1622float2(((const __nv_bfloat162*)&av10)[q]);
        yv = __bfloat1622float2(((const __nv_bfloat162*)&bv10)[q]);
        s1 += x.x * yv.x + x.y * yv.y;
        x = __bfloat1622float2(((const __nv_bfloat162*)&av11)[q]);
        yv = __bfloat1622float2(((const __nv_bfloat162*)&bv11)[q]);
        s1 += x.x * yv.x + x.y * yv.y;
    }
    #pragma unroll
    for (int o = 16; o > 0; o >>= 1) {
        s0 += __shfl_xor_sync(0xffffffffu, s0, o);
        s1 += __shfl_xor_sync(0xffffffffu, s1, o);
    }
    if (lane == 0) { g_sy[r0] = s0; g_sy[r1] = s1; }
}

// ---------------------------------------------------------------------------
// Logits GEMM (imgh @ txth^T) + fused softmax-partials epilogue.
// R10 configuration (best measured: 51.2us): 128x128 tile, 128 threads
// (4 warps 2x2, warp tile 64x64), occ 2, 3-stage cp.async ring with copies
// spread across kk, double-buffered k-fragments, smem-staged epilogue operands.
// ---------------------------------------------------------------------------
#define LG_SMEM 102912

__global__ __launch_bounds__(128, 2) void logits_mma(const int* __restrict__ labels,
                                                     const float* __restrict__ lsp)
{
    extern __shared__ char smem[];
    const uint32_t sb = s2u(smem);
    int*   slabC = (int*)(smem + 98304);
    int*   slabR = (int*)(smem + 98816);
    float* ssy   = (float*)(smem + 99328);
    float* pS    = (float*)(smem + 99840);
    float* pD    = (float*)(smem + 100864);
    const int m0 = blockIdx.y * 128, n0 = blockIdx.x * 128;
    const int tid = threadIdx.x;
    slabC[tid] = labels[n0 + tid];
    slabR[tid] = labels[m0 + tid];
    ssy[tid]   = g_sy[m0 + tid];

    const __nv_bfloat16* A = g_imgh + (size_t)m0 * EDIM;
    const __nv_bfloat16* B = g_txth + (size_t)n0 * EDIM;
    const int lane = tid & 31, warp = tid >> 5;
    const int l15 = lane & 15, lhi = lane >> 4;
    const int warp_m = warp >> 1, warp_n = warp & 1;   // 2 x 2

    float c[4][8][4] = {};          // 64 rows x 64 cols per warp
    uint32_t af[2][4][4], bf[2][4][4];

    const int arow = warp_m * 64 + l15;
    const int brow = warp_n * 64 + l15;

    #define LD_FRAGS(buf, abase, bbase, ch) do {                                   \
        _Pragma("unroll")                                                          \
        for (int mt = 0; mt < 4; mt++) {                                           \
            int r = arow + mt * 16;                                                \
            ldsm4(af[buf][mt], (abase) + (uint32_t)r * 128u +                      \
                  ((uint32_t)((ch) ^ (r & 7)) << 4));                              \
        }                                                                          \
        _Pragma("unroll")                                                          \
        for (int h = 0; h < 4; h++) {                                              \
            int r = brow + h * 16;                                                 \
            ldsm4(bf[buf][h], (bbase) + (uint32_t)r * 128u +                       \
                  ((uint32_t)((ch) ^ (r & 7)) << 4));                              \
        }                                                                          \
    } while (0)

    constexpr int ITERS = EDIM / 64;   // 8
    #pragma unroll
    for (int p = 0; p < 2; p++) {
        load_rows<128, EDIM, 128>(sb + p * 32768u,          A, p * 64);
        load_rows<128, EDIM, 128>(sb + p * 32768u + 16384u, B, p * 64);
        cp_commit();
    }
    cp_wait1();
    __syncthreads();
    LD_FRAGS(0, sb, sb + 16384u, lhi);   // stage 0, kk=0

    for (int s = 0; s < ITERS; s++) {
        const uint32_t abase = sb + (uint32_t)(s % 3) * 32768u;
        const uint32_t bbase = abase + 16384u;
        const bool pre = (s + 2 < ITERS);
        const uint32_t pa = sb + (uint32_t)((s + 2) % 3) * 32768u;
        #pragma unroll
        for (int kk = 0; kk < 4; kk++) {
            const int cur = kk & 1, nxt = cur ^ 1;
            if (kk < 3)
                LD_FRAGS(nxt, abase, bbase, (kk + 1) * 2 + lhi);
            if (pre) {
                load_q(kk, pa, pa + 16384u, A, B, (s + 2) * 64);
                if (kk == 3) cp_commit();
            }
            #pragma unroll
            for (int mt = 0; mt < 4; mt++)
                #pragma unroll
                for (int nt = 0; nt < 8; nt++)
                    mma16816(c[mt][nt], af[cur][mt],
                             bf[cur][nt >> 1][nt & 1], bf[cur][nt >> 1][2 + (nt & 1)]);
        }
        if (s + 1 < ITERS) {
            if (pre) cp_wait1(); else cp_wait0();
            __syncthreads();
            const uint32_t an = sb + (uint32_t)((s + 1) % 3) * 32768u;
            LD_FRAGS(0, an, an + 16384u, lhi);   // next stage kk=0 -> buf0
        }
    }
    __syncthreads();

    // ---- epilogue: exp2 + masked row-sum partials (operands from smem) ----
    const int g = lane >> 2, tig = lane & 3;
    const float scale = expf(__ldg(lsp));
    const float s2 = scale * 1.4426950408889634f;   // log2(e)*scale
    const float b2 = -s2;

    #pragma unroll
    for (int mt = 0; mt < 4; mt++) {
        const int rl = warp_m * 64 + mt * 16 + g;
        const int lab_lo = slabR[rl], lab_hi = slabR[rl + 8];
        const float sy_lo = ssy[rl], sy_hi = ssy[rl + 8];
        float Slo = 0.f, Dlo = 0.f, Shi = 0.f, Dhi = 0.f;
        #pragma unroll
        for (int nt = 0; nt < 8; nt++) {
            const int jl = warp_n * 64 + nt * 8 + tig * 2;
            const int lab0 = slabC[jl], lab1 = slabC[jl + 1];
            const int j0 = n0 + jl, j1 = j0 + 1;
            float v, e;
            v = c[mt][nt][0]; e = exp2f(fmaf(v, s2, b2)); Slo += e;
            if (lab0 != lab_lo && j0 != lab_lo && v > sy_lo) Dlo += e;
            v = c[mt][nt][1]; e = exp2f(fmaf(v, s2, b2)); Slo += e;
            if (lab1 != lab_lo && j1 != lab_lo && v > sy_lo) Dlo += e;
            v = c[mt][nt][2]; e = exp2f(fmaf(v, s2, b2)); Shi += e;
            if (lab0 != lab_hi && j0 != lab_hi && v > sy_hi) Dhi += e;
            v = c[mt][nt][3]; e = exp2f(fmaf(v, s2, b2)); Shi += e;
            if (lab1 != lab_hi && j1 != lab_hi && v > sy_hi) Dhi += e;
        }
        #pragma unroll
        for (int o = 1; o < 4; o <<= 1) {
            Slo += __shfl_xor_sync(0xffffffffu, Slo, o);
            Dlo += __shfl_xor_sync(0xffffffffu, Dlo, o);
            Shi += __shfl_xor_sync(0xffffffffu, Shi, o);
            Dhi += __shfl_xor_sync(0xffffffffu, Dhi, o);
        }
        if (tig == 0) {
            pS[rl * 2 + warp_n] = Slo;  pD[rl * 2 + warp_n] = Dlo;
            pS[(rl + 8) * 2 + warp_n] = Shi;  pD[(rl + 8) * 2 + warp_n] = Dhi;
        }
    }
    __syncthreads();
    {
        float S = pS[tid * 2] + pS[tid * 2 + 1];
        float D = pD[tid * 2] + pD[tid * 2 + 1];
        g_partS[(size_t)blockIdx.x * BROWS + m0 + tid] = S;
        g_partD[(size_t)blockIdx.x * BROWS + m0 + tid] = D;
    }
    #undef LD_FRAGS
}

// ---------------------------------------------------------------------------
// Per-row loss terms; each of 32 blocks emits one partial sum (deterministic).
// ---------------------------------------------------------------------------
__global__ void rowloss_k(const float* __restrict__ lsp)
{
    const int row = blockIdx.x * blockDim.x + threadIdx.x;   // 32 x 128
    const float scale = expf(*lsp);
    float S = 0.f, D = 0.f;
    #pragma unroll
    for (int t = 0; t < NT; t++) {
        S += g_partS[t * BROWS + row];
        D += g_partD[t * BROWS + row];
    }
    const float sy = g_sy[row] * scale;
    const float logp = (sy - scale) - logf(S);
    const float p = expf(logp);
    const float denom = D / S;
    const float cmp = (D > 0.0f) ? p / (denom + 1e-10f) : 0.0f;
    float v = cmp - logp;
    #pragma unroll
    for (int o = 16; o > 0; o >>= 1) v += __shfl_xor_sync(0xffffffffu, v, o);
    __shared__ float red[4];
    if ((threadIdx.x & 31) == 0) red[threadIdx.x >> 5] = v;
    __syncthreads();
    if (threadIdx.x == 0)
        g_row[blockIdx.x] = red[0] + red[1] + red[2] + red[3];
}

__global__ void final_k(float* __restrict__ out)
{
    const int lane = threadIdx.x;   // 32
    float s = g_row[lane];
    #pragma unroll
    for (int o = 16; o > 0; o >>= 1) s += __shfl_xor_sync(0xffffffffu, s, o);
    if (lane == 0) out[0] = s / (float)BROWS;
}

// ---------------------------------------------------------------------------
extern "C" void kernel_launch(void* const* d_in, const int* in_sizes, int n_in,
                              void* d_out, int out_size)
{
    const float* images = (const float*)d_in[0];
    const float* texts  = (const float*)d_in[1];
    const int*   labels = (const int*)d_in[2];
    const float* W_img  = (const float*)d_in[3];
    const float* W_txt  = (const float*)d_in[4];
    const float* lscale = (const float*)d_in[5];
    float* out = (float*)d_out;

    // Idempotent; needed for >48KB dynamic smem.
    cudaFuncSetAttribute(embed_norm_k, cudaFuncAttributeMaxDynamicSharedMemorySize, EN_SMEM);
    cudaFuncSetAttribute(logits_mma,   cudaFuncAttributeMaxDynamicSharedMemorySize, LG_SMEM);

    transpose2_k<<<dim3(EDIM / 32, DDIM / 64, 2), 256>>>(W_img, W_txt);

    embed_norm_k<<<dim3(BROWS / 64, 2), 256, EN_SMEM>>>(images, texts);

    sy_k<<<BROWS / 16, 256>>>(labels);

    logits_mma<<<dim3(NT, NT), 128, LG_SMEM>>>(labels, lscale);

    rowloss_k<<<32, 128>>>(lscale);
    final_k<<<1, 32>>>(out);
}